// round 13
// baseline (speedup 1.0000x reference)
#include <cuda_runtime.h>
#include <cuda_bf16.h>
#include <cuda_fp16.h>
#include <cstdint>
#include <cstddef>

// ---------------------------------------------------------------- constants
#define DQ   128          // head dim d == projection dim m
#define QN   512          // queries
#define NKEY 131072       // keys
#define KH   256          // fp16 halves per augmented row: [0:128) mse*vn, [128:256) sign*c
#define NCHUNK 4          // 4 x 64-col K chunks (main gemm)
#define TM 128
#define TN 128
#define EPSV 1e-8f
// sqrt(pi/2)/128
#define SCALEC 0.009791516697777347f

// ---------------------------------------------------------------- scratch
__device__ uint4 g_Kaug4[(size_t)NKEY * KH / 8];        // 64 MB fp16
__device__ uint4 g_Qaug4[(size_t)QN * KH / 8];          // 256 KB fp16
__device__ uint4 g_Sh4[DQ * DQ / 8];                    // S hi fp16, [t][j]
__device__ uint4 g_Sl4[DQ * DQ / 8];                    // S lo fp16, [t][j]

// ---------------------------------------------------------------- ptx utils
__device__ __forceinline__ uint32_t smem_u32(const void* p) {
    uint32_t a;
    asm("{ .reg .u64 tmp; cvta.to.shared.u64 tmp, %1; cvt.u32.u64 %0, tmp; }" : "=r"(a) : "l"(p));
    return a;
}
__device__ __forceinline__ uint32_t h2pack(float a, float b) {
    __half2 h = __floats2half2_rn(a, b);   // a -> low half (memory-first)
    return *(uint32_t*)&h;
}

#define SWZ128(off) ((off) ^ (((off) >> 3) & 0x70))

__device__ __forceinline__ void ldsm_x4(uint32_t& r0, uint32_t& r1, uint32_t& r2, uint32_t& r3,
                                        uint32_t addr) {
    asm volatile("ldmatrix.sync.aligned.m8n8.x4.shared.b16 {%0,%1,%2,%3}, [%4];"
        : "=r"(r0), "=r"(r1), "=r"(r2), "=r"(r3) : "r"(addr));
}
__device__ __forceinline__ void mma16816(float* c, const uint32_t* a, const uint32_t* b) {
    asm volatile(
        "mma.sync.aligned.m16n8k16.row.col.f32.f16.f16.f32 "
        "{%0,%1,%2,%3}, {%4,%5,%6,%7}, {%8,%9}, {%0,%1,%2,%3};"
        : "+f"(c[0]), "+f"(c[1]), "+f"(c[2]), "+f"(c[3])
        : "r"(a[0]), "r"(a[1]), "r"(a[2]), "r"(a[3]), "r"(b[0]), "r"(b[1]));
}
// fp16-accumulate variant (rt=8): D,C are 2 regs = 4 halves
__device__ __forceinline__ void mma16816_h(uint32_t* c, const uint32_t* a, const uint32_t* b) {
    asm volatile(
        "mma.sync.aligned.m16n8k16.row.col.f16.f16.f16.f16 "
        "{%0,%1}, {%2,%3,%4,%5}, {%6,%7}, {%0,%1};"
        : "+r"(c[0]), "+r"(c[1])
        : "r"(a[0]), "r"(a[1]), "r"(a[2]), "r"(a[3]), "r"(b[0]), "r"(b[1]));
}
__device__ __forceinline__ void cp_async16(uint32_t saddr, const void* gptr) {
    asm volatile("cp.async.cg.shared.global [%0], [%1], 16;" :: "r"(saddr), "l"(gptr) : "memory");
}
#define CP_COMMIT() asm volatile("cp.async.commit_group;" ::: "memory")
#define CP_WAIT(n)  asm volatile("cp.async.wait_group %0;" :: "n"(n) : "memory")

// ================================================================ kernel 1
// S -> fp16 hi/lo, [t][j] layout
__global__ void k_prep_S(const float* __restrict__ S) {
    int t = blockIdx.x, j = threadIdx.x;
    float v = S[t * DQ + j];
    __half h = __float2half_rn(v);
    __half l = __float2half_rn(v - __half2float(h));
    ((__half*)g_Sh4)[t * DQ + j] = h;
    ((__half*)g_Sl4)[t * DQ + j] = l;
}

// ================================================================ kernel 2
// per query: Qaug(fp16) = [q (128) | q@S^T (128)]   (fp32 math)
__global__ void k_prep_query(const float* __restrict__ query, const float* __restrict__ S) {
    __shared__ float qs[DQ];
    int q = blockIdx.x, t = threadIdx.x;
    qs[t] = query[q * DQ + t];
    __syncthreads();
    float acc = 0.0f;
    const float* srow = S + t * DQ;
    #pragma unroll 8
    for (int j = 0; j < DQ; j++) acc = fmaf(qs[j], srow[j], acc);
    __half* Qa = (__half*)g_Qaug4 + (size_t)q * KH;
    Qa[t]       = __float2half_rn(qs[t]);
    Qa[128 + t] = __float2half_rn(acc);
}

// ================================================================ kernel 3
// PERSISTENT fused key prep (round-8 measured-best version, verbatim).
// 296 CTAs (2/SM), 256 thr, loop over 64-key tiles. S hi/lo staged once.
#define PITCHB 272
#define SM_AH  0
#define SM_AL  (64 * PITCHB)                  // 17408
#define SM_SH  (2 * 64 * PITCHB)              // 34816
#define SM_SL  (SM_SH + 128 * PITCHB)         // 69632
#define SM_CS  (SM_SL + 128 * PITCHB)         // 104448
#define PF_SMEM (SM_CS + 256)                 // 104704
#define PREP_GRID 296
__global__ void __launch_bounds__(256, 2) k_prep_keys(const float* __restrict__ keys,
                                                      const float* __restrict__ cb) {
    extern __shared__ char sm[];
    uint32_t sb = smem_u32(sm);
    float* cs = (float*)(sm + SM_CS);
    int tid = threadIdx.x, wid = tid >> 5, lane = tid & 31;

    // ---- stage S hi/lo once
    for (int i = tid; i < 2048; i += 256) {
        int t = i >> 4, u = i & 15;
        cp_async16(sb + SM_SH + t * PITCHB + u * 16, g_Sh4 + i);
        cp_async16(sb + SM_SL + t * PITCHB + u * 16, g_Sl4 + i);
    }
    CP_COMMIT();

    float c0 = cb[0], c1 = cb[1], c2 = cb[2], c3 = cb[3];
    float t01 = 0.5f * (c0 + c1), t12 = 0.5f * (c1 + c2), t23 = 0.5f * (c2 + c3);

    // thread roles
    int row = tid >> 2, qtr = tid & 3;                  // phase 1
    int wm = wid >> 2, wn = wid & 3;                    // phase 2: 2(M) x 4(N)
    int rowA = (lane & 7) + ((lane >> 3) & 1) * 8;
    int byteA = (lane >> 4) * 16;
    int rowB = (lane & 7) + (lane >> 4) * 8;
    int byteB = ((lane >> 3) & 1) * 16;
    int tq = lane >> 2, tn2 = (lane & 3) * 2;

    CP_WAIT(0);
    __syncthreads();

    for (int tile = blockIdx.x; tile < NKEY / 64; tile += PREP_GRID) {
        int key0 = tile * 64;
        int n = key0 + row;

        // ---- phase 1
        const float4* kp = (const float4*)(keys + (size_t)n * DQ + qtr * 32);
        float4 kf[8];
        float ss = 0.0f;
        #pragma unroll
        for (int g = 0; g < 8; g++) {
            kf[g] = kp[g];
            ss = fmaf(kf[g].x, kf[g].x, ss);
            ss = fmaf(kf[g].y, kf[g].y, ss);
            ss = fmaf(kf[g].z, kf[g].z, ss);
            ss = fmaf(kf[g].w, kf[g].w, ss);
        }
        ss += __shfl_xor_sync(0xffffffffu, ss, 1);
        ss += __shfl_xor_sync(0xffffffffu, ss, 2);
        float vn = sqrtf(ss);
        float inv = 1.0f / (vn + EPSV);

        float rs = 0.0f;
        uint32_t hwm[16], hwh[16], hwl[16];
        #pragma unroll
        for (int g = 0; g < 8; g++) {
            float xv[4] = {kf[g].x, kf[g].y, kf[g].z, kf[g].w};
            float rv[4], mv[4], lv[4];
            #pragma unroll
            for (int e = 0; e < 4; e++) {
                float x = xv[e] * inv;
                float xm = c0;
                if (x > t01) xm = c1;
                if (x > t12) xm = c2;
                if (x > t23) xm = c3;
                float r = x - xm;
                rs = fmaf(r, r, rs);
                mv[e] = xm * vn;
                __half rh = __float2half_rn(r);
                rv[e] = __half2float(rh);
                lv[e] = r - rv[e];
            }
            hwm[g * 2 + 0] = h2pack(mv[0], mv[1]);
            hwm[g * 2 + 1] = h2pack(mv[2], mv[3]);
            hwh[g * 2 + 0] = h2pack(rv[0], rv[1]);
            hwh[g * 2 + 1] = h2pack(rv[2], rv[3]);
            hwl[g * 2 + 0] = h2pack(lv[0], lv[1]);
            hwl[g * 2 + 1] = h2pack(lv[2], lv[3]);
        }
        {
            uint4* Ka = g_Kaug4 + (size_t)n * (KH / 8) + qtr * 4;
            #pragma unroll
            for (int w = 0; w < 4; w++)
                Ka[w] = make_uint4(hwm[w * 4 + 0], hwm[w * 4 + 1], hwm[w * 4 + 2], hwm[w * 4 + 3]);
        }
        {
            uint4* Ap = (uint4*)(sm + SM_AH + row * PITCHB + qtr * 64);
            uint4* Lp = (uint4*)(sm + SM_AL + row * PITCHB + qtr * 64);
            #pragma unroll
            for (int w = 0; w < 4; w++) {
                Ap[w] = make_uint4(hwh[w * 4 + 0], hwh[w * 4 + 1], hwh[w * 4 + 2], hwh[w * 4 + 3]);
                Lp[w] = make_uint4(hwl[w * 4 + 0], hwl[w * 4 + 1], hwl[w * 4 + 2], hwl[w * 4 + 3]);
            }
        }
        rs += __shfl_xor_sync(0xffffffffu, rs, 1);
        rs += __shfl_xor_sync(0xffffffffu, rs, 2);
        if (qtr == 0) cs[row] = sqrtf(rs) * SCALEC * vn;
        __syncthreads();

        // ---- phase 2: HMMA P[64 x 128] = R @ S^T, 3 segments (fp32 acc — sign-critical)
        float acc[2][4][4];
        #pragma unroll
        for (int i = 0; i < 2; i++)
            #pragma unroll
            for (int j = 0; j < 4; j++)
                #pragma unroll
                for (int r = 0; r < 4; r++) acc[i][j][r] = 0.0f;

        #pragma unroll
        for (int seg = 0; seg < 3; seg++) {
            uint32_t aB = sb + (seg == 2 ? SM_AL : SM_AH);
            uint32_t bB = sb + (seg == 1 ? SM_SL : SM_SH);
            #pragma unroll
            for (int k16 = 0; k16 < 8; k16++) {
                int kb = k16 * 32;
                uint32_t af[2][4], bf[2][4];
                #pragma unroll
                for (int im = 0; im < 2; im++)
                    ldsm_x4(af[im][0], af[im][1], af[im][2], af[im][3],
                            aB + (wm * 32 + im * 16 + rowA) * PITCHB + kb + byteA);
                #pragma unroll
                for (int pr = 0; pr < 2; pr++)
                    ldsm_x4(bf[pr][0], bf[pr][1], bf[pr][2], bf[pr][3],
                            bB + (wn * 32 + pr * 16 + rowB) * PITCHB + kb + byteB);
                #pragma unroll
                for (int im = 0; im < 2; im++)
                    #pragma unroll
                    for (int in = 0; in < 4; in++)
                        mma16816(acc[im][in], af[im], &bf[in >> 1][(in & 1) * 2]);
            }
        }
        __syncthreads();   // all A-tile ldsm reads done (same-wm warps share A rows)

        // ---- signs * c -> smem (reuse A-hi region), then coalesced to Kaug
        #pragma unroll
        for (int im = 0; im < 2; im++) {
            int r0 = wm * 32 + im * 16 + tq;
            float ca = cs[r0], cb2 = cs[r0 + 8];
            #pragma unroll
            for (int in = 0; in < 4; in++) {
                int t = wn * 32 + in * 8 + tn2;
                *(uint32_t*)(sm + SM_AH + r0 * PITCHB + t * 2) =
                    h2pack(acc[im][in][0] >= 0.0f ? ca : -ca,
                           acc[im][in][1] >= 0.0f ? ca : -ca);
                *(uint32_t*)(sm + SM_AH + (r0 + 8) * PITCHB + t * 2) =
                    h2pack(acc[im][in][2] >= 0.0f ? cb2 : -cb2,
                           acc[im][in][3] >= 0.0f ? cb2 : -cb2);
            }
        }
        __syncthreads();

        // 64 rows x 16 uint4 (256 B of signs per key) = 1024 uint4
        #pragma unroll
        for (int i = 0; i < 4; i++) {
            int idx = tid + i * 256;
            int r = idx >> 4, u = idx & 15;
            uint4 v = *(const uint4*)(sm + SM_AH + r * PITCHB + u * 16);
            g_Kaug4[(size_t)(key0 + r) * (KH / 8) + 16 + u] = v;
        }
        __syncthreads();   // before next tile's phase-1 smem writes
    }
}

// ================================================================ kernel 4
// out[512, 131072] = Qaug @ Kaug^T, K=256. CTA 128x128, 256 thr, 8 warps =
// 2(M) x 4(N), warp tile 64x32, double-buffered cp.async, 2 CTAs/SM.
// NEW: fp16-accumulate per 64-col chunk (rt=8), folded into fp32 master acc.
#define GE_STAGE 32768             // A 16KB + B 16KB
#define GE_SMEM  (2 * GE_STAGE)
__global__ void __launch_bounds__(256) k_gemm(float* __restrict__ out) {
    extern __shared__ char sm[];
    uint32_t sb = smem_u32(sm);
    int tid = threadIdx.x, wid = tid >> 5, lane = tid & 31;
    int nstrip = blockIdx.x >> 2;       // N-major: 4 M-tiles adjacent share B via L2
    int mtile  = blockIdx.x & 3;
    int key0 = nstrip * TN;

    int wm = wid >> 2, wn = wid & 3;    // warp tile: rows wm*64.., cols wn*32..

    int rowA = (lane & 7) + ((lane >> 3) & 1) * 8;   // A frags
    int byteA = (lane >> 4) * 16;
    int rowB = (lane & 7) + (lane >> 4) * 8;         // B frags
    int byteB = ((lane >> 3) & 1) * 16;

    float acc[4][4][4];
    #pragma unroll
    for (int i = 0; i < 4; i++)
        #pragma unroll
        for (int j = 0; j < 4; j++)
            #pragma unroll
            for (int r = 0; r < 4; r++) acc[i][j][r] = 0.0f;

    const uint4* QA = g_Qaug4;
    const uint4* KA = g_Kaug4;

    // chunk c covers fp16 cols [c*64, c*64+64) = uint4 [c*8, c*8+8) of the 32/row
    #define PREFETCH(c, buf) do { \
        int col8_ = (c) * 8; \
        uint32_t base_ = sb + (buf) * GE_STAGE; \
        _Pragma("unroll") \
        for (int it_ = 0; it_ < 8; it_++) { \
            int idx_ = tid + it_ * 256; \
            int half_ = idx_ >> 10; \
            int w_ = idx_ & 1023; \
            int row_ = w_ >> 3, u_ = w_ & 7; \
            const uint4* gp_; \
            if (half_ == 0) gp_ = QA + (size_t)(mtile * TM + row_) * 32 + col8_ + u_; \
            else            gp_ = KA + (size_t)(key0 + row_) * 32 + col8_ + u_; \
            uint32_t off_ = ((uint32_t)(row_ >> 3) << 10) | ((uint32_t)(row_ & 7) << 7) | ((uint32_t)u_ << 4); \
            off_ = SWZ128(off_); \
            cp_async16(base_ + half_ * 16384 + off_, gp_); \
        } \
        CP_COMMIT(); \
    } while (0)

    PREFETCH(0, 0);

    for (int c = 0; c < NCHUNK; c++) {
        if (c + 1 < NCHUNK) { PREFETCH(c + 1, (c + 1) & 1); CP_WAIT(1); }
        else                { CP_WAIT(0); }
        __syncthreads();

        uint32_t aBase = sb + (c & 1) * GE_STAGE;
        uint32_t bBase = aBase + 16384;

        // two im-halves to bound live fp16 accumulators (keep regs < 128)
        #pragma unroll
        for (int h = 0; h < 2; h++) {
            uint32_t ch[2][4][2];            // [im2][in][reg] fp16 accum (4 halves each)
            #pragma unroll
            for (int i = 0; i < 2; i++)
                #pragma unroll
                for (int j = 0; j < 4; j++) { ch[i][j][0] = 0u; ch[i][j][1] = 0u; }

            #pragma unroll
            for (int k16 = 0; k16 < 4; k16++) {
                int kb = k16 * 32;
                uint32_t af[2][4], bf[2][4];
                #pragma unroll
                for (int im2 = 0; im2 < 2; im2++) {
                    int r = wm * 64 + (h * 2 + im2) * 16 + rowA;
                    uint32_t off = ((uint32_t)(r >> 3) << 10) | ((uint32_t)(r & 7) << 7) |
                                   (uint32_t)(kb + byteA);
                    ldsm_x4(af[im2][0], af[im2][1], af[im2][2], af[im2][3], aBase + SWZ128(off));
                }
                #pragma unroll
                for (int pr = 0; pr < 2; pr++) {
                    int r = wn * 32 + pr * 16 + rowB;
                    uint32_t off = ((uint32_t)(r >> 3) << 10) | ((uint32_t)(r & 7) << 7) |
                                   (uint32_t)(kb + byteB);
                    ldsm_x4(bf[pr][0], bf[pr][1], bf[pr][2], bf[pr][3], bBase + SWZ128(off));
                }
                #pragma unroll
                for (int im2 = 0; im2 < 2; im2++) {
                    #pragma unroll
                    for (int in = 0; in < 4; in++) {
                        mma16816_h(ch[im2][in], af[im2], &bf[in >> 1][(in & 1) * 2]);
                    }
                }
            }
            // fold fp16 chunk accumulators into fp32 master
            #pragma unroll
            for (int im2 = 0; im2 < 2; im2++) {
                #pragma unroll
                for (int in = 0; in < 4; in++) {
                    float2 f01 = __half22float2(*reinterpret_cast<__half2*>(&ch[im2][in][0]));
                    float2 f23 = __half22float2(*reinterpret_cast<__half2*>(&ch[im2][in][1]));
                    acc[h * 2 + im2][in][0] += f01.x;
                    acc[h * 2 + im2][in][1] += f01.y;
                    acc[h * 2 + im2][in][2] += f23.x;
                    acc[h * 2 + im2][in][3] += f23.y;
                }
            }
        }
        __syncthreads();
    }

    // ---- epilogue: direct fp32 stores ----
    int tq = lane >> 2, tn2 = (lane & 3) * 2;
    #pragma unroll
    for (int im = 0; im < 4; im++) {
        #pragma unroll
        for (int in = 0; in < 4; in++) {
            int m = mtile * TM + wm * 64 + im * 16 + tq;
            int n = key0 + wn * 32 + in * 8 + tn2;
            float2 v0 = make_float2(acc[im][in][0], acc[im][in][1]);
            float2 v1 = make_float2(acc[im][in][2], acc[im][in][3]);
            *(float2*)(out + (size_t)m * NKEY + n) = v0;
            *(float2*)(out + (size_t)(m + 8) * NKEY + n) = v1;
        }
    }
    #undef PREFETCH
}

// ================================================================ launch
extern "C" void kernel_launch(void* const* d_in, const int* in_sizes, int n_in,
                              void* d_out, int out_size) {
    const float* query = (const float*)d_in[0];
    const float* keys  = (const float*)d_in[1];
    const float* cb    = (const float*)d_in[2];
    const float* S     = (const float*)d_in[3];
    float* out = (float*)d_out;

    static bool attr_done = false;
    if (!attr_done) {
        cudaFuncSetAttribute(k_prep_keys, cudaFuncAttributeMaxDynamicSharedMemorySize, PF_SMEM);
        cudaFuncSetAttribute(k_gemm, cudaFuncAttributeMaxDynamicSharedMemorySize, GE_SMEM);
        attr_done = true;
    }

    k_prep_S<<<DQ, DQ>>>(S);
    k_prep_query<<<QN, 128>>>(query, S);
    k_prep_keys<<<PREP_GRID, 256, PF_SMEM>>>(keys, cb);
    k_gemm<<<(NKEY / TN) * (QN / TM), 256, GE_SMEM>>>(out);
}

// round 14
// speedup vs baseline: 1.1773x; 1.1773x over previous
#include <cuda_runtime.h>
#include <cuda_bf16.h>
#include <cuda_fp16.h>
#include <cstdint>
#include <cstddef>

// ---------------------------------------------------------------- constants
#define DQ   128          // head dim d == projection dim m
#define QN   512          // queries
#define NKEY 131072       // keys
#define KH   256          // fp16 halves per augmented row: [0:128) mse*vn, [128:256) sign*c
#define NCHUNK 4          // 4 x 64-col K chunks (main gemm)
#define TM 128
#define TN 128
#define EPSV 1e-8f
// sqrt(pi/2)/128
#define SCALEC 0.009791516697777347f

// ---------------------------------------------------------------- scratch
__device__ uint4 g_Kaug4[(size_t)NKEY * KH / 8];        // 64 MB fp16
__device__ uint4 g_Qaug4[(size_t)QN * KH / 8];          // 256 KB fp16
__device__ uint4 g_Sh4[DQ * DQ / 8];                    // S hi fp16, [t][j]
__device__ uint4 g_Sl4[DQ * DQ / 8];                    // S lo fp16, [t][j]

// ---------------------------------------------------------------- ptx utils
__device__ __forceinline__ uint32_t smem_u32(const void* p) {
    uint32_t a;
    asm("{ .reg .u64 tmp; cvta.to.shared.u64 tmp, %1; cvt.u32.u64 %0, tmp; }" : "=r"(a) : "l"(p));
    return a;
}
__device__ __forceinline__ uint32_t h2pack(float a, float b) {
    __half2 h = __floats2half2_rn(a, b);   // a -> low half (memory-first)
    return *(uint32_t*)&h;
}

#define SWZ128(off) ((off) ^ (((off) >> 3) & 0x70))

__device__ __forceinline__ void ldsm_x4(uint32_t& r0, uint32_t& r1, uint32_t& r2, uint32_t& r3,
                                        uint32_t addr) {
    asm volatile("ldmatrix.sync.aligned.m8n8.x4.shared.b16 {%0,%1,%2,%3}, [%4];"
        : "=r"(r0), "=r"(r1), "=r"(r2), "=r"(r3) : "r"(addr));
}
__device__ __forceinline__ void mma16816(float* c, const uint32_t* a, const uint32_t* b) {
    asm volatile(
        "mma.sync.aligned.m16n8k16.row.col.f32.f16.f16.f32 "
        "{%0,%1,%2,%3}, {%4,%5,%6,%7}, {%8,%9}, {%0,%1,%2,%3};"
        : "+f"(c[0]), "+f"(c[1]), "+f"(c[2]), "+f"(c[3])
        : "r"(a[0]), "r"(a[1]), "r"(a[2]), "r"(a[3]), "r"(b[0]), "r"(b[1]));
}
__device__ __forceinline__ void cp_async16(uint32_t saddr, const void* gptr) {
    asm volatile("cp.async.cg.shared.global [%0], [%1], 16;" :: "r"(saddr), "l"(gptr) : "memory");
}
#define CP_COMMIT() asm volatile("cp.async.commit_group;" ::: "memory")
#define CP_WAIT(n)  asm volatile("cp.async.wait_group %0;" :: "n"(n) : "memory")

// ================================================================ kernel 1
// S -> fp16 hi/lo, [t][j] layout
__global__ void k_prep_S(const float* __restrict__ S) {
    int t = blockIdx.x, j = threadIdx.x;
    float v = S[t * DQ + j];
    __half h = __float2half_rn(v);
    __half l = __float2half_rn(v - __half2float(h));
    ((__half*)g_Sh4)[t * DQ + j] = h;
    ((__half*)g_Sl4)[t * DQ + j] = l;
}

// ================================================================ kernel 2
// per query: Qaug(fp16) = [q (128) | q@S^T (128)]   (fp32 math)
__global__ void k_prep_query(const float* __restrict__ query, const float* __restrict__ S) {
    __shared__ float qs[DQ];
    int q = blockIdx.x, t = threadIdx.x;
    qs[t] = query[q * DQ + t];
    __syncthreads();
    float acc = 0.0f;
    const float* srow = S + t * DQ;
    #pragma unroll 8
    for (int j = 0; j < DQ; j++) acc = fmaf(qs[j], srow[j], acc);
    __half* Qa = (__half*)g_Qaug4 + (size_t)q * KH;
    Qa[t]       = __float2half_rn(qs[t]);
    Qa[128 + t] = __float2half_rn(acc);
}

// ================================================================ kernel 3
// PERSISTENT fused key prep (round-8 measured-best body), parameterized by
// [tile0, tile0+ntiles) so halves can be pipelined against the GEMM.
#define PITCHB 272
#define SM_AH  0
#define SM_AL  (64 * PITCHB)                  // 17408
#define SM_SH  (2 * 64 * PITCHB)              // 34816
#define SM_SL  (SM_SH + 128 * PITCHB)         // 69632
#define SM_CS  (SM_SL + 128 * PITCHB)         // 104448
#define PF_SMEM (SM_CS + 256)                 // 104704
#define PREP_GRID 296
__global__ void __launch_bounds__(256, 2) k_prep_keys(const float* __restrict__ keys,
                                                      const float* __restrict__ cb,
                                                      int tile0, int ntiles) {
    extern __shared__ char sm[];
    uint32_t sb = smem_u32(sm);
    float* cs = (float*)(sm + SM_CS);
    int tid = threadIdx.x, wid = tid >> 5, lane = tid & 31;

    // ---- stage S hi/lo once
    for (int i = tid; i < 2048; i += 256) {
        int t = i >> 4, u = i & 15;
        cp_async16(sb + SM_SH + t * PITCHB + u * 16, g_Sh4 + i);
        cp_async16(sb + SM_SL + t * PITCHB + u * 16, g_Sl4 + i);
    }
    CP_COMMIT();

    float c0 = cb[0], c1 = cb[1], c2 = cb[2], c3 = cb[3];
    float t01 = 0.5f * (c0 + c1), t12 = 0.5f * (c1 + c2), t23 = 0.5f * (c2 + c3);

    // thread roles
    int row = tid >> 2, qtr = tid & 3;                  // phase 1
    int wm = wid >> 2, wn = wid & 3;                    // phase 2: 2(M) x 4(N)
    int rowA = (lane & 7) + ((lane >> 3) & 1) * 8;
    int byteA = (lane >> 4) * 16;
    int rowB = (lane & 7) + (lane >> 4) * 8;
    int byteB = ((lane >> 3) & 1) * 16;
    int tq = lane >> 2, tn2 = (lane & 3) * 2;

    CP_WAIT(0);
    __syncthreads();

    for (int tile = tile0 + blockIdx.x; tile < tile0 + ntiles; tile += PREP_GRID) {
        int key0 = tile * 64;
        int n = key0 + row;

        // ---- phase 1
        const float4* kp = (const float4*)(keys + (size_t)n * DQ + qtr * 32);
        float4 kf[8];
        float ss = 0.0f;
        #pragma unroll
        for (int g = 0; g < 8; g++) {
            kf[g] = kp[g];
            ss = fmaf(kf[g].x, kf[g].x, ss);
            ss = fmaf(kf[g].y, kf[g].y, ss);
            ss = fmaf(kf[g].z, kf[g].z, ss);
            ss = fmaf(kf[g].w, kf[g].w, ss);
        }
        ss += __shfl_xor_sync(0xffffffffu, ss, 1);
        ss += __shfl_xor_sync(0xffffffffu, ss, 2);
        float vn = sqrtf(ss);
        float inv = 1.0f / (vn + EPSV);

        float rs = 0.0f;
        uint32_t hwm[16], hwh[16], hwl[16];
        #pragma unroll
        for (int g = 0; g < 8; g++) {
            float xv[4] = {kf[g].x, kf[g].y, kf[g].z, kf[g].w};
            float rv[4], mv[4], lv[4];
            #pragma unroll
            for (int e = 0; e < 4; e++) {
                float x = xv[e] * inv;
                float xm = c0;
                if (x > t01) xm = c1;
                if (x > t12) xm = c2;
                if (x > t23) xm = c3;
                float r = x - xm;
                rs = fmaf(r, r, rs);
                mv[e] = xm * vn;
                __half rh = __float2half_rn(r);
                rv[e] = __half2float(rh);
                lv[e] = r - rv[e];
            }
            hwm[g * 2 + 0] = h2pack(mv[0], mv[1]);
            hwm[g * 2 + 1] = h2pack(mv[2], mv[3]);
            hwh[g * 2 + 0] = h2pack(rv[0], rv[1]);
            hwh[g * 2 + 1] = h2pack(rv[2], rv[3]);
            hwl[g * 2 + 0] = h2pack(lv[0], lv[1]);
            hwl[g * 2 + 1] = h2pack(lv[2], lv[3]);
        }
        {
            uint4* Ka = g_Kaug4 + (size_t)n * (KH / 8) + qtr * 4;
            #pragma unroll
            for (int w = 0; w < 4; w++)
                Ka[w] = make_uint4(hwm[w * 4 + 0], hwm[w * 4 + 1], hwm[w * 4 + 2], hwm[w * 4 + 3]);
        }
        {
            uint4* Ap = (uint4*)(sm + SM_AH + row * PITCHB + qtr * 64);
            uint4* Lp = (uint4*)(sm + SM_AL + row * PITCHB + qtr * 64);
            #pragma unroll
            for (int w = 0; w < 4; w++) {
                Ap[w] = make_uint4(hwh[w * 4 + 0], hwh[w * 4 + 1], hwh[w * 4 + 2], hwh[w * 4 + 3]);
                Lp[w] = make_uint4(hwl[w * 4 + 0], hwl[w * 4 + 1], hwl[w * 4 + 2], hwl[w * 4 + 3]);
            }
        }
        rs += __shfl_xor_sync(0xffffffffu, rs, 1);
        rs += __shfl_xor_sync(0xffffffffu, rs, 2);
        if (qtr == 0) cs[row] = sqrtf(rs) * SCALEC * vn;
        __syncthreads();

        // ---- phase 2: HMMA P[64 x 128] = R @ S^T, 3 segments (fp32 acc)
        float acc[2][4][4];
        #pragma unroll
        for (int i = 0; i < 2; i++)
            #pragma unroll
            for (int j = 0; j < 4; j++)
                #pragma unroll
                for (int r = 0; r < 4; r++) acc[i][j][r] = 0.0f;

        #pragma unroll
        for (int seg = 0; seg < 3; seg++) {
            uint32_t aB = sb + (seg == 2 ? SM_AL : SM_AH);
            uint32_t bB = sb + (seg == 1 ? SM_SL : SM_SH);
            #pragma unroll
            for (int k16 = 0; k16 < 8; k16++) {
                int kb = k16 * 32;
                uint32_t af[2][4], bf[2][4];
                #pragma unroll
                for (int im = 0; im < 2; im++)
                    ldsm_x4(af[im][0], af[im][1], af[im][2], af[im][3],
                            aB + (wm * 32 + im * 16 + rowA) * PITCHB + kb + byteA);
                #pragma unroll
                for (int pr = 0; pr < 2; pr++)
                    ldsm_x4(bf[pr][0], bf[pr][1], bf[pr][2], bf[pr][3],
                            bB + (wn * 32 + pr * 16 + rowB) * PITCHB + kb + byteB);
                #pragma unroll
                for (int im = 0; im < 2; im++)
                    #pragma unroll
                    for (int in = 0; in < 4; in++)
                        mma16816(acc[im][in], af[im], &bf[in >> 1][(in & 1) * 2]);
            }
        }
        __syncthreads();   // all A-tile ldsm reads done (same-wm warps share A rows)

        // ---- signs * c -> smem (reuse A-hi region), then coalesced to Kaug
        #pragma unroll
        for (int im = 0; im < 2; im++) {
            int r0 = wm * 32 + im * 16 + tq;
            float ca = cs[r0], cb2 = cs[r0 + 8];
            #pragma unroll
            for (int in = 0; in < 4; in++) {
                int t = wn * 32 + in * 8 + tn2;
                *(uint32_t*)(sm + SM_AH + r0 * PITCHB + t * 2) =
                    h2pack(acc[im][in][0] >= 0.0f ? ca : -ca,
                           acc[im][in][1] >= 0.0f ? ca : -ca);
                *(uint32_t*)(sm + SM_AH + (r0 + 8) * PITCHB + t * 2) =
                    h2pack(acc[im][in][2] >= 0.0f ? cb2 : -cb2,
                           acc[im][in][3] >= 0.0f ? cb2 : -cb2);
            }
        }
        __syncthreads();

        // 64 rows x 16 uint4 (256 B of signs per key) = 1024 uint4
        #pragma unroll
        for (int i = 0; i < 4; i++) {
            int idx = tid + i * 256;
            int r = idx >> 4, u = idx & 15;
            uint4 v = *(const uint4*)(sm + SM_AH + r * PITCHB + u * 16);
            g_Kaug4[(size_t)(key0 + r) * (KH / 8) + 16 + u] = v;
        }
        __syncthreads();   // before next tile's phase-1 smem writes
    }
}

// ================================================================ kernel 4
// out[512, 131072] = Qaug @ Kaug^T, K=256 — PROVEN fp32-acc config (112 us,
// measured 3x): CTA 128x128, 256 thr, 8 warps = 2(M)x4(N), warp tile 64x32,
// double-buffered cp.async, 2 CTAs/SM. key_base selects the key half.
#define GE_STAGE 32768             // A 16KB + B 16KB
#define GE_SMEM  (2 * GE_STAGE)
__global__ void __launch_bounds__(256) k_gemm(float* __restrict__ out, int key_base) {
    extern __shared__ char sm[];
    uint32_t sb = smem_u32(sm);
    int tid = threadIdx.x, wid = tid >> 5, lane = tid & 31;
    int nstrip = blockIdx.x >> 2;       // N-major: 4 M-tiles adjacent share B via L2
    int mtile  = blockIdx.x & 3;
    int key0 = key_base + nstrip * TN;

    int wm = wid >> 2, wn = wid & 3;    // warp tile: rows wm*64.., cols wn*32..

    int rowA = (lane & 7) + ((lane >> 3) & 1) * 8;   // A frags
    int byteA = (lane >> 4) * 16;
    int rowB = (lane & 7) + (lane >> 4) * 8;         // B frags
    int byteB = ((lane >> 3) & 1) * 16;

    float acc[4][4][4];
    #pragma unroll
    for (int i = 0; i < 4; i++)
        #pragma unroll
        for (int j = 0; j < 4; j++)
            #pragma unroll
            for (int r = 0; r < 4; r++) acc[i][j][r] = 0.0f;

    const uint4* QA = g_Qaug4;
    const uint4* KA = g_Kaug4;

    // chunk c covers fp16 cols [c*64, c*64+64) = uint4 [c*8, c*8+8) of the 32/row
    #define PREFETCH(c, buf) do { \
        int col8_ = (c) * 8; \
        uint32_t base_ = sb + (buf) * GE_STAGE; \
        _Pragma("unroll") \
        for (int it_ = 0; it_ < 8; it_++) { \
            int idx_ = tid + it_ * 256; \
            int half_ = idx_ >> 10; \
            int w_ = idx_ & 1023; \
            int row_ = w_ >> 3, u_ = w_ & 7; \
            const uint4* gp_; \
            if (half_ == 0) gp_ = QA + (size_t)(mtile * TM + row_) * 32 + col8_ + u_; \
            else            gp_ = KA + (size_t)(key0 + row_) * 32 + col8_ + u_; \
            uint32_t off_ = ((uint32_t)(row_ >> 3) << 10) | ((uint32_t)(row_ & 7) << 7) | ((uint32_t)u_ << 4); \
            off_ = SWZ128(off_); \
            cp_async16(base_ + half_ * 16384 + off_, gp_); \
        } \
        CP_COMMIT(); \
    } while (0)

    PREFETCH(0, 0);

    for (int c = 0; c < NCHUNK; c++) {
        if (c + 1 < NCHUNK) { PREFETCH(c + 1, (c + 1) & 1); CP_WAIT(1); }
        else                { CP_WAIT(0); }
        __syncthreads();

        uint32_t aBase = sb + (c & 1) * GE_STAGE;
        uint32_t bBase = aBase + 16384;

        #pragma unroll
        for (int k16 = 0; k16 < 4; k16++) {
            int kb = k16 * 32;
            uint32_t af[4][4], bf[2][4];
            #pragma unroll
            for (int im = 0; im < 4; im++) {
                int r = wm * 64 + im * 16 + rowA;
                uint32_t off = ((uint32_t)(r >> 3) << 10) | ((uint32_t)(r & 7) << 7) |
                               (uint32_t)(kb + byteA);
                ldsm_x4(af[im][0], af[im][1], af[im][2], af[im][3], aBase + SWZ128(off));
            }
            #pragma unroll
            for (int pr = 0; pr < 2; pr++) {
                int r = wn * 32 + pr * 16 + rowB;
                uint32_t off = ((uint32_t)(r >> 3) << 10) | ((uint32_t)(r & 7) << 7) |
                               (uint32_t)(kb + byteB);
                ldsm_x4(bf[pr][0], bf[pr][1], bf[pr][2], bf[pr][3], bBase + SWZ128(off));
            }
            #pragma unroll
            for (int im = 0; im < 4; im++) {
                #pragma unroll
                for (int in = 0; in < 4; in++) {
                    mma16816(acc[im][in], af[im], &bf[in >> 1][(in & 1) * 2]);
                }
            }
        }
        __syncthreads();
    }

    // ---- epilogue: direct fp32 stores ----
    int tq = lane >> 2, tn2 = (lane & 3) * 2;
    #pragma unroll
    for (int im = 0; im < 4; im++) {
        #pragma unroll
        for (int in = 0; in < 4; in++) {
            int m = mtile * TM + wm * 64 + im * 16 + tq;
            int n = key0 + wn * 32 + in * 8 + tn2;
            float2 v0 = make_float2(acc[im][in][0], acc[im][in][1]);
            float2 v1 = make_float2(acc[im][in][2], acc[im][in][3]);
            *(float2*)(out + (size_t)m * NKEY + n) = v0;
            *(float2*)(out + (size_t)(m + 8) * NKEY + n) = v1;
        }
    }
    #undef PREFETCH
}

// ================================================================ launch
// Pipelined halves: prep(h1) -> [gemm(h1) on s2 || prep(h2) on s0] -> gemm(h2)
#define HALF_TILES 1024            // 65536 keys per half
#define HALF_KEYS  65536
extern "C" void kernel_launch(void* const* d_in, const int* in_sizes, int n_in,
                              void* d_out, int out_size) {
    const float* query = (const float*)d_in[0];
    const float* keys  = (const float*)d_in[1];
    const float* cb    = (const float*)d_in[2];
    const float* S     = (const float*)d_in[3];
    float* out = (float*)d_out;

    static bool init_done = false;
    static cudaStream_t s2;
    static cudaEvent_t evFork, evJoin;
    if (!init_done) {
        cudaFuncSetAttribute(k_prep_keys, cudaFuncAttributeMaxDynamicSharedMemorySize, PF_SMEM);
        cudaFuncSetAttribute(k_gemm, cudaFuncAttributeMaxDynamicSharedMemorySize, GE_SMEM);
        cudaStreamCreateWithFlags(&s2, cudaStreamNonBlocking);
        cudaEventCreateWithFlags(&evFork, cudaEventDisableTiming);
        cudaEventCreateWithFlags(&evJoin, cudaEventDisableTiming);
        init_done = true;
    }

    k_prep_S<<<DQ, DQ>>>(S);
    k_prep_query<<<QN, 128>>>(query, S);

    // half 1 prep (stream 0)
    k_prep_keys<<<PREP_GRID, 256, PF_SMEM>>>(keys, cb, 0, HALF_TILES);

    // fork: gemm(half1) on s2 concurrent with prep(half2) on stream 0
    cudaEventRecord(evFork, 0);
    cudaStreamWaitEvent(s2, evFork, 0);
    k_gemm<<<(HALF_KEYS / TN) * (QN / TM), 256, GE_SMEM, s2>>>(out, 0);
    k_prep_keys<<<PREP_GRID, 256, PF_SMEM>>>(keys, cb, HALF_TILES, HALF_TILES);

    // join, then gemm(half2) on stream 0
    cudaEventRecord(evJoin, s2);
    cudaStreamWaitEvent(0, evJoin, 0);
    k_gemm<<<(HALF_KEYS / TN) * (QN / TM), 256, GE_SMEM>>>(out, HALF_KEYS);
}

// round 15
// speedup vs baseline: 1.2295x; 1.0444x over previous
#include <cuda_runtime.h>
#include <cuda_bf16.h>
#include <cuda_fp16.h>
#include <cstdint>
#include <cstddef>

// ---------------------------------------------------------------- constants
#define DQ   128          // head dim d == projection dim m
#define QN   512          // queries
#define NKEY 131072       // keys
#define KH   256          // fp16 halves per augmented row: [0:128) mse*vn, [128:256) sign*c
#define NCHUNK 4          // 4 x 64-col K chunks (main gemm)
#define TM 128
#define TN 128
#define EPSV 1e-8f
// sqrt(pi/2)/128
#define SCALEC 0.009791516697777347f

// ---------------------------------------------------------------- scratch
__device__ uint4 g_Kaug4[(size_t)NKEY * KH / 8];        // 64 MB fp16
__device__ uint4 g_Qaug4[(size_t)QN * KH / 8];          // 256 KB fp16
__device__ uint4 g_Sh4[DQ * DQ / 8];                    // S hi fp16, [t][j]
__device__ uint4 g_Sl4[DQ * DQ / 8];                    // S lo fp16, [t][j]

// ---------------------------------------------------------------- ptx utils
__device__ __forceinline__ uint32_t smem_u32(const void* p) {
    uint32_t a;
    asm("{ .reg .u64 tmp; cvta.to.shared.u64 tmp, %1; cvt.u32.u64 %0, tmp; }" : "=r"(a) : "l"(p));
    return a;
}
__device__ __forceinline__ uint32_t h2pack(float a, float b) {
    __half2 h = __floats2half2_rn(a, b);   // a -> low half (memory-first)
    return *(uint32_t*)&h;
}

#define SWZ128(off) ((off) ^ (((off) >> 3) & 0x70))

__device__ __forceinline__ void ldsm_x4(uint32_t& r0, uint32_t& r1, uint32_t& r2, uint32_t& r3,
                                        uint32_t addr) {
    asm volatile("ldmatrix.sync.aligned.m8n8.x4.shared.b16 {%0,%1,%2,%3}, [%4];"
        : "=r"(r0), "=r"(r1), "=r"(r2), "=r"(r3) : "r"(addr));
}
__device__ __forceinline__ void mma16816(float* c, const uint32_t* a, const uint32_t* b) {
    asm volatile(
        "mma.sync.aligned.m16n8k16.row.col.f32.f16.f16.f32 "
        "{%0,%1,%2,%3}, {%4,%5,%6,%7}, {%8,%9}, {%0,%1,%2,%3};"
        : "+f"(c[0]), "+f"(c[1]), "+f"(c[2]), "+f"(c[3])
        : "r"(a[0]), "r"(a[1]), "r"(a[2]), "r"(a[3]), "r"(b[0]), "r"(b[1]));
}
__device__ __forceinline__ void cp_async16(uint32_t saddr, const void* gptr) {
    asm volatile("cp.async.cg.shared.global [%0], [%1], 16;" :: "r"(saddr), "l"(gptr) : "memory");
}
#define CP_COMMIT() asm volatile("cp.async.commit_group;" ::: "memory")
#define CP_WAIT(n)  asm volatile("cp.async.wait_group %0;" :: "n"(n) : "memory")

// ================================================================ kernel 1
// S -> fp16 hi/lo, [t][j] layout
__global__ void k_prep_S(const float* __restrict__ S) {
    int t = blockIdx.x, j = threadIdx.x;
    float v = S[t * DQ + j];
    __half h = __float2half_rn(v);
    __half l = __float2half_rn(v - __half2float(h));
    ((__half*)g_Sh4)[t * DQ + j] = h;
    ((__half*)g_Sl4)[t * DQ + j] = l;
}

// ================================================================ kernel 2
// per query: Qaug(fp16) = [q (128) | q@S^T (128)]   (fp32 math)
__global__ void k_prep_query(const float* __restrict__ query, const float* __restrict__ S) {
    __shared__ float qs[DQ];
    int q = blockIdx.x, t = threadIdx.x;
    qs[t] = query[q * DQ + t];
    __syncthreads();
    float acc = 0.0f;
    const float* srow = S + t * DQ;
    #pragma unroll 8
    for (int j = 0; j < DQ; j++) acc = fmaf(qs[j], srow[j], acc);
    __half* Qa = (__half*)g_Qaug4 + (size_t)q * KH;
    Qa[t]       = __float2half_rn(qs[t]);
    Qa[128 + t] = __float2half_rn(acc);
}

// ================================================================ kernel 3
// PERSISTENT fused key prep (round-8 measured-best body), parameterized by
// [tile0, tile0+ntiles); strides by gridDim.x so reduced grids (for overlap
// co-residency with the GEMM) are correct.
#define PITCHB 272
#define SM_AH  0
#define SM_AL  (64 * PITCHB)                  // 17408
#define SM_SH  (2 * 64 * PITCHB)              // 34816
#define SM_SL  (SM_SH + 128 * PITCHB)         // 69632
#define SM_CS  (SM_SL + 128 * PITCHB)         // 104448
#define PF_SMEM (SM_CS + 256)                 // 104704
#define PREP_GRID  296                        // full-speed: 2 CTAs/SM
#define PREP_GRID1 148                        // overlap: 1 CTA/SM, leaves 126KB for gemm
__global__ void __launch_bounds__(256, 2) k_prep_keys(const float* __restrict__ keys,
                                                      const float* __restrict__ cb,
                                                      int tile0, int ntiles) {
    extern __shared__ char sm[];
    uint32_t sb = smem_u32(sm);
    float* cs = (float*)(sm + SM_CS);
    int tid = threadIdx.x, wid = tid >> 5, lane = tid & 31;

    // ---- stage S hi/lo once
    for (int i = tid; i < 2048; i += 256) {
        int t = i >> 4, u = i & 15;
        cp_async16(sb + SM_SH + t * PITCHB + u * 16, g_Sh4 + i);
        cp_async16(sb + SM_SL + t * PITCHB + u * 16, g_Sl4 + i);
    }
    CP_COMMIT();

    float c0 = cb[0], c1 = cb[1], c2 = cb[2], c3 = cb[3];
    float t01 = 0.5f * (c0 + c1), t12 = 0.5f * (c1 + c2), t23 = 0.5f * (c2 + c3);

    // thread roles
    int row = tid >> 2, qtr = tid & 3;                  // phase 1
    int wm = wid >> 2, wn = wid & 3;                    // phase 2: 2(M) x 4(N)
    int rowA = (lane & 7) + ((lane >> 3) & 1) * 8;
    int byteA = (lane >> 4) * 16;
    int rowB = (lane & 7) + (lane >> 4) * 8;
    int byteB = ((lane >> 3) & 1) * 16;
    int tq = lane >> 2, tn2 = (lane & 3) * 2;

    CP_WAIT(0);
    __syncthreads();

    for (int tile = tile0 + blockIdx.x; tile < tile0 + ntiles; tile += gridDim.x) {
        int key0 = tile * 64;
        int n = key0 + row;

        // ---- phase 1
        const float4* kp = (const float4*)(keys + (size_t)n * DQ + qtr * 32);
        float4 kf[8];
        float ss = 0.0f;
        #pragma unroll
        for (int g = 0; g < 8; g++) {
            kf[g] = kp[g];
            ss = fmaf(kf[g].x, kf[g].x, ss);
            ss = fmaf(kf[g].y, kf[g].y, ss);
            ss = fmaf(kf[g].z, kf[g].z, ss);
            ss = fmaf(kf[g].w, kf[g].w, ss);
        }
        ss += __shfl_xor_sync(0xffffffffu, ss, 1);
        ss += __shfl_xor_sync(0xffffffffu, ss, 2);
        float vn = sqrtf(ss);
        float inv = 1.0f / (vn + EPSV);

        float rs = 0.0f;
        uint32_t hwm[16], hwh[16], hwl[16];
        #pragma unroll
        for (int g = 0; g < 8; g++) {
            float xv[4] = {kf[g].x, kf[g].y, kf[g].z, kf[g].w};
            float rv[4], mv[4], lv[4];
            #pragma unroll
            for (int e = 0; e < 4; e++) {
                float x = xv[e] * inv;
                float xm = c0;
                if (x > t01) xm = c1;
                if (x > t12) xm = c2;
                if (x > t23) xm = c3;
                float r = x - xm;
                rs = fmaf(r, r, rs);
                mv[e] = xm * vn;
                __half rh = __float2half_rn(r);
                rv[e] = __half2float(rh);
                lv[e] = r - rv[e];
            }
            hwm[g * 2 + 0] = h2pack(mv[0], mv[1]);
            hwm[g * 2 + 1] = h2pack(mv[2], mv[3]);
            hwh[g * 2 + 0] = h2pack(rv[0], rv[1]);
            hwh[g * 2 + 1] = h2pack(rv[2], rv[3]);
            hwl[g * 2 + 0] = h2pack(lv[0], lv[1]);
            hwl[g * 2 + 1] = h2pack(lv[2], lv[3]);
        }
        {
            uint4* Ka = g_Kaug4 + (size_t)n * (KH / 8) + qtr * 4;
            #pragma unroll
            for (int w = 0; w < 4; w++)
                Ka[w] = make_uint4(hwm[w * 4 + 0], hwm[w * 4 + 1], hwm[w * 4 + 2], hwm[w * 4 + 3]);
        }
        {
            uint4* Ap = (uint4*)(sm + SM_AH + row * PITCHB + qtr * 64);
            uint4* Lp = (uint4*)(sm + SM_AL + row * PITCHB + qtr * 64);
            #pragma unroll
            for (int w = 0; w < 4; w++) {
                Ap[w] = make_uint4(hwh[w * 4 + 0], hwh[w * 4 + 1], hwh[w * 4 + 2], hwh[w * 4 + 3]);
                Lp[w] = make_uint4(hwl[w * 4 + 0], hwl[w * 4 + 1], hwl[w * 4 + 2], hwl[w * 4 + 3]);
            }
        }
        rs += __shfl_xor_sync(0xffffffffu, rs, 1);
        rs += __shfl_xor_sync(0xffffffffu, rs, 2);
        if (qtr == 0) cs[row] = sqrtf(rs) * SCALEC * vn;
        __syncthreads();

        // ---- phase 2: HMMA P[64 x 128] = R @ S^T, 3 segments (fp32 acc)
        float acc[2][4][4];
        #pragma unroll
        for (int i = 0; i < 2; i++)
            #pragma unroll
            for (int j = 0; j < 4; j++)
                #pragma unroll
                for (int r = 0; r < 4; r++) acc[i][j][r] = 0.0f;

        #pragma unroll
        for (int seg = 0; seg < 3; seg++) {
            uint32_t aB = sb + (seg == 2 ? SM_AL : SM_AH);
            uint32_t bB = sb + (seg == 1 ? SM_SL : SM_SH);
            #pragma unroll
            for (int k16 = 0; k16 < 8; k16++) {
                int kb = k16 * 32;
                uint32_t af[2][4], bf[2][4];
                #pragma unroll
                for (int im = 0; im < 2; im++)
                    ldsm_x4(af[im][0], af[im][1], af[im][2], af[im][3],
                            aB + (wm * 32 + im * 16 + rowA) * PITCHB + kb + byteA);
                #pragma unroll
                for (int pr = 0; pr < 2; pr++)
                    ldsm_x4(bf[pr][0], bf[pr][1], bf[pr][2], bf[pr][3],
                            bB + (wn * 32 + pr * 16 + rowB) * PITCHB + kb + byteB);
                #pragma unroll
                for (int im = 0; im < 2; im++)
                    #pragma unroll
                    for (int in = 0; in < 4; in++)
                        mma16816(acc[im][in], af[im], &bf[in >> 1][(in & 1) * 2]);
            }
        }
        __syncthreads();   // all A-tile ldsm reads done (same-wm warps share A rows)

        // ---- signs * c -> smem (reuse A-hi region), then coalesced to Kaug
        #pragma unroll
        for (int im = 0; im < 2; im++) {
            int r0 = wm * 32 + im * 16 + tq;
            float ca = cs[r0], cb2 = cs[r0 + 8];
            #pragma unroll
            for (int in = 0; in < 4; in++) {
                int t = wn * 32 + in * 8 + tn2;
                *(uint32_t*)(sm + SM_AH + r0 * PITCHB + t * 2) =
                    h2pack(acc[im][in][0] >= 0.0f ? ca : -ca,
                           acc[im][in][1] >= 0.0f ? ca : -ca);
                *(uint32_t*)(sm + SM_AH + (r0 + 8) * PITCHB + t * 2) =
                    h2pack(acc[im][in][2] >= 0.0f ? cb2 : -cb2,
                           acc[im][in][3] >= 0.0f ? cb2 : -cb2);
            }
        }
        __syncthreads();

        // 64 rows x 16 uint4 (256 B of signs per key) = 1024 uint4
        #pragma unroll
        for (int i = 0; i < 4; i++) {
            int idx = tid + i * 256;
            int r = idx >> 4, u = idx & 15;
            uint4 v = *(const uint4*)(sm + SM_AH + r * PITCHB + u * 16);
            g_Kaug4[(size_t)(key0 + r) * (KH / 8) + 16 + u] = v;
        }
        __syncthreads();   // before next tile's phase-1 smem writes
    }
}

// ================================================================ kernel 4
// out[512, 131072] = Qaug @ Kaug^T, K=256 — PROVEN fp32-acc config (112 us,
// measured 3x): CTA 128x128, 256 thr, 8 warps = 2(M)x4(N), warp tile 64x32,
// double-buffered cp.async, 2 CTAs/SM. key_base selects the key half.
#define GE_STAGE 32768             // A 16KB + B 16KB
#define GE_SMEM  (2 * GE_STAGE)
__global__ void __launch_bounds__(256) k_gemm(float* __restrict__ out, int key_base) {
    extern __shared__ char sm[];
    uint32_t sb = smem_u32(sm);
    int tid = threadIdx.x, wid = tid >> 5, lane = tid & 31;
    int nstrip = blockIdx.x >> 2;       // N-major: 4 M-tiles adjacent share B via L2
    int mtile  = blockIdx.x & 3;
    int key0 = key_base + nstrip * TN;

    int wm = wid >> 2, wn = wid & 3;    // warp tile: rows wm*64.., cols wn*32..

    int rowA = (lane & 7) + ((lane >> 3) & 1) * 8;   // A frags
    int byteA = (lane >> 4) * 16;
    int rowB = (lane & 7) + (lane >> 4) * 8;         // B frags
    int byteB = ((lane >> 3) & 1) * 16;

    float acc[4][4][4];
    #pragma unroll
    for (int i = 0; i < 4; i++)
        #pragma unroll
        for (int j = 0; j < 4; j++)
            #pragma unroll
            for (int r = 0; r < 4; r++) acc[i][j][r] = 0.0f;

    const uint4* QA = g_Qaug4;
    const uint4* KA = g_Kaug4;

    // chunk c covers fp16 cols [c*64, c*64+64) = uint4 [c*8, c*8+8) of the 32/row
    #define PREFETCH(c, buf) do { \
        int col8_ = (c) * 8; \
        uint32_t base_ = sb + (buf) * GE_STAGE; \
        _Pragma("unroll") \
        for (int it_ = 0; it_ < 8; it_++) { \
            int idx_ = tid + it_ * 256; \
            int half_ = idx_ >> 10; \
            int w_ = idx_ & 1023; \
            int row_ = w_ >> 3, u_ = w_ & 7; \
            const uint4* gp_; \
            if (half_ == 0) gp_ = QA + (size_t)(mtile * TM + row_) * 32 + col8_ + u_; \
            else            gp_ = KA + (size_t)(key0 + row_) * 32 + col8_ + u_; \
            uint32_t off_ = ((uint32_t)(row_ >> 3) << 10) | ((uint32_t)(row_ & 7) << 7) | ((uint32_t)u_ << 4); \
            off_ = SWZ128(off_); \
            cp_async16(base_ + half_ * 16384 + off_, gp_); \
        } \
        CP_COMMIT(); \
    } while (0)

    PREFETCH(0, 0);

    for (int c = 0; c < NCHUNK; c++) {
        if (c + 1 < NCHUNK) { PREFETCH(c + 1, (c + 1) & 1); CP_WAIT(1); }
        else                { CP_WAIT(0); }
        __syncthreads();

        uint32_t aBase = sb + (c & 1) * GE_STAGE;
        uint32_t bBase = aBase + 16384;

        #pragma unroll
        for (int k16 = 0; k16 < 4; k16++) {
            int kb = k16 * 32;
            uint32_t af[4][4], bf[2][4];
            #pragma unroll
            for (int im = 0; im < 4; im++) {
                int r = wm * 64 + im * 16 + rowA;
                uint32_t off = ((uint32_t)(r >> 3) << 10) | ((uint32_t)(r & 7) << 7) |
                               (uint32_t)(kb + byteA);
                ldsm_x4(af[im][0], af[im][1], af[im][2], af[im][3], aBase + SWZ128(off));
            }
            #pragma unroll
            for (int pr = 0; pr < 2; pr++) {
                int r = wn * 32 + pr * 16 + rowB;
                uint32_t off = ((uint32_t)(r >> 3) << 10) | ((uint32_t)(r & 7) << 7) |
                               (uint32_t)(kb + byteB);
                ldsm_x4(bf[pr][0], bf[pr][1], bf[pr][2], bf[pr][3], bBase + SWZ128(off));
            }
            #pragma unroll
            for (int im = 0; im < 4; im++) {
                #pragma unroll
                for (int in = 0; in < 4; in++) {
                    mma16816(acc[im][in], af[im], &bf[in >> 1][(in & 1) * 2]);
                }
            }
        }
        __syncthreads();
    }

    // ---- epilogue: direct fp32 stores ----
    int tq = lane >> 2, tn2 = (lane & 3) * 2;
    #pragma unroll
    for (int im = 0; im < 4; im++) {
        #pragma unroll
        for (int in = 0; in < 4; in++) {
            int m = mtile * TM + wm * 64 + im * 16 + tq;
            int n = key0 + wn * 32 + in * 8 + tn2;
            float2 v0 = make_float2(acc[im][in][0], acc[im][in][1]);
            float2 v1 = make_float2(acc[im][in][2], acc[im][in][3]);
            *(float2*)(out + (size_t)m * NKEY + n) = v0;
            *(float2*)(out + (size_t)(m + 8) * NKEY + n) = v1;
        }
    }
    #undef PREFETCH
}

// ================================================================ launch
// Partitioned overlap:
//   prep(h1, 296 CTAs)  ->  [ prep(h2, 148 CTAs = 1/SM, 102KB)  ||
//                             gemm(h1) on s2 (64KB CTAs fit in the 126KB gap) ]
//   -> gemm(h2) on s0 (starts right after prep h2; overlaps gemm h1 drain)
//   -> final join of s2 into s0 (required for valid capture)
#define H1_TILES 1024
#define H2_TILES 1024
#define H1_KEYS  65536
#define H2_KEYS  65536
extern "C" void kernel_launch(void* const* d_in, const int* in_sizes, int n_in,
                              void* d_out, int out_size) {
    const float* query = (const float*)d_in[0];
    const float* keys  = (const float*)d_in[1];
    const float* cb    = (const float*)d_in[2];
    const float* S     = (const float*)d_in[3];
    float* out = (float*)d_out;

    static bool init_done = false;
    static cudaStream_t s2;
    static cudaEvent_t evFork, evJoin;
    if (!init_done) {
        cudaFuncSetAttribute(k_prep_keys, cudaFuncAttributeMaxDynamicSharedMemorySize, PF_SMEM);
        cudaFuncSetAttribute(k_gemm, cudaFuncAttributeMaxDynamicSharedMemorySize, GE_SMEM);
        cudaStreamCreateWithFlags(&s2, cudaStreamNonBlocking);
        cudaEventCreateWithFlags(&evFork, cudaEventDisableTiming);
        cudaEventCreateWithFlags(&evJoin, cudaEventDisableTiming);
        init_done = true;
    }

    k_prep_S<<<DQ, DQ>>>(S);
    k_prep_query<<<QN, 128>>>(query, S);

    // half 1 prep at full speed (2 CTAs/SM)
    k_prep_keys<<<PREP_GRID, 256, PF_SMEM>>>(keys, cb, 0, H1_TILES);
    cudaEventRecord(evFork, 0);

    // half 2 prep at 1 CTA/SM — recorded first so its CTAs place first,
    // leaving 126KB/SM for concurrent gemm CTAs
    k_prep_keys<<<PREP_GRID1, 256, PF_SMEM>>>(keys, cb, H1_TILES, H2_TILES);

    // gemm(half 1) concurrent on s2
    cudaStreamWaitEvent(s2, evFork, 0);
    k_gemm<<<(H1_KEYS / TN) * (QN / TM), 256, GE_SMEM, s2>>>(out, 0);

    // gemm(half 2) on s0 — depends only on prep h2 (stream order);
    // overlaps gemm h1's drain (disjoint output regions)
    k_gemm<<<(H2_KEYS / TN) * (QN / TM), 256, GE_SMEM>>>(out, H1_KEYS);

    // final cross-stream join (capture requires forked work to rejoin)
    cudaEventRecord(evJoin, s2);
    cudaStreamWaitEvent(0, evJoin, 0);
}

// round 16
// speedup vs baseline: 1.2520x; 1.0183x over previous
#include <cuda_runtime.h>
#include <cuda_bf16.h>
#include <cuda_fp16.h>
#include <cstdint>
#include <cstddef>

// ---------------------------------------------------------------- constants
#define DQ   128          // head dim d == projection dim m
#define QN   512          // queries
#define NKEY 131072       // keys
#define KH   256          // fp16 halves per augmented row: [0:128) mse*vn, [128:256) sign*c
#define NCHUNK 4          // 4 x 64-col K chunks (main gemm)
#define TM 128
#define TN 128
#define EPSV 1e-8f
// sqrt(pi/2)/128
#define SCALEC 0.009791516697777347f

// ---------------------------------------------------------------- scratch
__device__ uint4 g_Kaug4[(size_t)NKEY * KH / 8];        // 64 MB fp16
__device__ uint4 g_Qaug4[(size_t)QN * KH / 8];          // 256 KB fp16
__device__ uint4 g_Sh4[DQ * DQ / 8];                    // S hi fp16, [t][j]
__device__ uint4 g_Sl4[DQ * DQ / 8];                    // S lo fp16, [t][j]

// ---------------------------------------------------------------- ptx utils
__device__ __forceinline__ uint32_t smem_u32(const void* p) {
    uint32_t a;
    asm("{ .reg .u64 tmp; cvta.to.shared.u64 tmp, %1; cvt.u32.u64 %0, tmp; }" : "=r"(a) : "l"(p));
    return a;
}
__device__ __forceinline__ uint32_t h2pack(float a, float b) {
    __half2 h = __floats2half2_rn(a, b);   // a -> low half (memory-first)
    return *(uint32_t*)&h;
}

#define SWZ128(off) ((off) ^ (((off) >> 3) & 0x70))

__device__ __forceinline__ void ldsm_x4(uint32_t& r0, uint32_t& r1, uint32_t& r2, uint32_t& r3,
                                        uint32_t addr) {
    asm volatile("ldmatrix.sync.aligned.m8n8.x4.shared.b16 {%0,%1,%2,%3}, [%4];"
        : "=r"(r0), "=r"(r1), "=r"(r2), "=r"(r3) : "r"(addr));
}
__device__ __forceinline__ void mma16816(float* c, const uint32_t* a, const uint32_t* b) {
    asm volatile(
        "mma.sync.aligned.m16n8k16.row.col.f32.f16.f16.f32 "
        "{%0,%1,%2,%3}, {%4,%5,%6,%7}, {%8,%9}, {%0,%1,%2,%3};"
        : "+f"(c[0]), "+f"(c[1]), "+f"(c[2]), "+f"(c[3])
        : "r"(a[0]), "r"(a[1]), "r"(a[2]), "r"(a[3]), "r"(b[0]), "r"(b[1]));
}
__device__ __forceinline__ void cp_async16(uint32_t saddr, const void* gptr) {
    asm volatile("cp.async.cg.shared.global [%0], [%1], 16;" :: "r"(saddr), "l"(gptr) : "memory");
}
#define CP_COMMIT() asm volatile("cp.async.commit_group;" ::: "memory")
#define CP_WAIT(n)  asm volatile("cp.async.wait_group %0;" :: "n"(n) : "memory")

// ================================================================ kernel 1
// S -> fp16 hi/lo, [t][j] layout
__global__ void k_prep_S(const float* __restrict__ S) {
    int t = blockIdx.x, j = threadIdx.x;
    float v = S[t * DQ + j];
    __half h = __float2half_rn(v);
    __half l = __float2half_rn(v - __half2float(h));
    ((__half*)g_Sh4)[t * DQ + j] = h;
    ((__half*)g_Sl4)[t * DQ + j] = l;
}

// ================================================================ kernel 2
// per query: Qaug(fp16) = [q (128) | q@S^T (128)]   (fp32 math)
__global__ void k_prep_query(const float* __restrict__ query, const float* __restrict__ S) {
    __shared__ float qs[DQ];
    int q = blockIdx.x, t = threadIdx.x;
    qs[t] = query[q * DQ + t];
    __syncthreads();
    float acc = 0.0f;
    const float* srow = S + t * DQ;
    #pragma unroll 8
    for (int j = 0; j < DQ; j++) acc = fmaf(qs[j], srow[j], acc);
    __half* Qa = (__half*)g_Qaug4 + (size_t)q * KH;
    Qa[t]       = __float2half_rn(qs[t]);
    Qa[128 + t] = __float2half_rn(acc);
}

// ================================================================ kernel 3
// PERSISTENT fused key prep — WIDE tiles: 128 keys/tile, 512 threads,
// 16 warps, 1 CTA/SM (prep is per-tile latency-bound; throughput was measured
// invariant to CTA count, so double the warps sharing one barrier chain).
//  phase 1: norms, quantize, mse fp16 -> Kaug; residual hi/lo fp16 -> smem
//  phase 2: P[128x128] = R @ S^T via 3-segment fp16 HMMA split (fp32 acc);
//           signs -> smem -> coalesced Kaug
#define PITCHB 272
#define SM_AH  0
#define SM_AL  (128 * PITCHB)                 // 34816
#define SM_SH  (2 * 128 * PITCHB)             // 69632
#define SM_SL  (SM_SH + 128 * PITCHB)         // 104448
#define SM_CS  (SM_SL + 128 * PITCHB)         // 139264
#define PF_SMEM (SM_CS + 512)                 // 139776
#define PREP_GRID 148
#define PREP_THREADS 512
#define TILE_KEYS 128
__global__ void __launch_bounds__(PREP_THREADS, 1) k_prep_keys(const float* __restrict__ keys,
                                                               const float* __restrict__ cb) {
    extern __shared__ char sm[];
    uint32_t sb = smem_u32(sm);
    float* cs = (float*)(sm + SM_CS);
    int tid = threadIdx.x, wid = tid >> 5, lane = tid & 31;

    // ---- stage S hi/lo once (2048 uint4 each)
    for (int i = tid; i < 2048; i += PREP_THREADS) {
        int t = i >> 4, u = i & 15;
        cp_async16(sb + SM_SH + t * PITCHB + u * 16, g_Sh4 + i);
        cp_async16(sb + SM_SL + t * PITCHB + u * 16, g_Sl4 + i);
    }
    CP_COMMIT();

    float c0 = cb[0], c1 = cb[1], c2 = cb[2], c3 = cb[3];
    float t01 = 0.5f * (c0 + c1), t12 = 0.5f * (c1 + c2), t23 = 0.5f * (c2 + c3);

    // thread roles
    int row = tid >> 2, qtr = tid & 3;                  // phase 1: rows 0..127
    int wm = wid >> 2, wn = wid & 3;                    // phase 2: 4(M) x 4(N)
    int rowA = (lane & 7) + ((lane >> 3) & 1) * 8;
    int byteA = (lane >> 4) * 16;
    int rowB = (lane & 7) + (lane >> 4) * 8;
    int byteB = ((lane >> 3) & 1) * 16;
    int tq = lane >> 2, tn2 = (lane & 3) * 2;

    CP_WAIT(0);
    __syncthreads();

    for (int tile = blockIdx.x; tile < NKEY / TILE_KEYS; tile += gridDim.x) {
        int key0 = tile * TILE_KEYS;
        int n = key0 + row;

        // ---- phase 1 (per-thread code identical to the proven 64-key version)
        const float4* kp = (const float4*)(keys + (size_t)n * DQ + qtr * 32);
        float4 kf[8];
        float ss = 0.0f;
        #pragma unroll
        for (int g = 0; g < 8; g++) {
            kf[g] = kp[g];
            ss = fmaf(kf[g].x, kf[g].x, ss);
            ss = fmaf(kf[g].y, kf[g].y, ss);
            ss = fmaf(kf[g].z, kf[g].z, ss);
            ss = fmaf(kf[g].w, kf[g].w, ss);
        }
        ss += __shfl_xor_sync(0xffffffffu, ss, 1);
        ss += __shfl_xor_sync(0xffffffffu, ss, 2);
        float vn = sqrtf(ss);
        float inv = 1.0f / (vn + EPSV);

        float rs = 0.0f;
        uint32_t hwm[16], hwh[16], hwl[16];
        #pragma unroll
        for (int g = 0; g < 8; g++) {
            float xv[4] = {kf[g].x, kf[g].y, kf[g].z, kf[g].w};
            float rv[4], mv[4], lv[4];
            #pragma unroll
            for (int e = 0; e < 4; e++) {
                float x = xv[e] * inv;
                float xm = c0;
                if (x > t01) xm = c1;
                if (x > t12) xm = c2;
                if (x > t23) xm = c3;
                float r = x - xm;
                rs = fmaf(r, r, rs);
                mv[e] = xm * vn;
                __half rh = __float2half_rn(r);
                rv[e] = __half2float(rh);
                lv[e] = r - rv[e];
            }
            hwm[g * 2 + 0] = h2pack(mv[0], mv[1]);
            hwm[g * 2 + 1] = h2pack(mv[2], mv[3]);
            hwh[g * 2 + 0] = h2pack(rv[0], rv[1]);
            hwh[g * 2 + 1] = h2pack(rv[2], rv[3]);
            hwl[g * 2 + 0] = h2pack(lv[0], lv[1]);
            hwl[g * 2 + 1] = h2pack(lv[2], lv[3]);
        }
        {
            uint4* Ka = g_Kaug4 + (size_t)n * (KH / 8) + qtr * 4;
            #pragma unroll
            for (int w = 0; w < 4; w++)
                Ka[w] = make_uint4(hwm[w * 4 + 0], hwm[w * 4 + 1], hwm[w * 4 + 2], hwm[w * 4 + 3]);
        }
        {
            uint4* Ap = (uint4*)(sm + SM_AH + row * PITCHB + qtr * 64);
            uint4* Lp = (uint4*)(sm + SM_AL + row * PITCHB + qtr * 64);
            #pragma unroll
            for (int w = 0; w < 4; w++) {
                Ap[w] = make_uint4(hwh[w * 4 + 0], hwh[w * 4 + 1], hwh[w * 4 + 2], hwh[w * 4 + 3]);
                Lp[w] = make_uint4(hwl[w * 4 + 0], hwl[w * 4 + 1], hwl[w * 4 + 2], hwl[w * 4 + 3]);
            }
        }
        rs += __shfl_xor_sync(0xffffffffu, rs, 1);
        rs += __shfl_xor_sync(0xffffffffu, rs, 2);
        if (qtr == 0) cs[row] = sqrtf(rs) * SCALEC * vn;
        __syncthreads();

        // ---- phase 2: HMMA P[128 x 128] = R @ S^T, 3 segments (fp32 acc)
        // 16 warps = 4(M) x 4(N), warp tile 32x32
        float acc[2][4][4];
        #pragma unroll
        for (int i = 0; i < 2; i++)
            #pragma unroll
            for (int j = 0; j < 4; j++)
                #pragma unroll
                for (int r = 0; r < 4; r++) acc[i][j][r] = 0.0f;

        #pragma unroll
        for (int seg = 0; seg < 3; seg++) {
            uint32_t aB = sb + (seg == 2 ? SM_AL : SM_AH);
            uint32_t bB = sb + (seg == 1 ? SM_SL : SM_SH);
            #pragma unroll
            for (int k16 = 0; k16 < 8; k16++) {
                int kb = k16 * 32;
                uint32_t af[2][4], bf[2][4];
                #pragma unroll
                for (int im = 0; im < 2; im++)
                    ldsm_x4(af[im][0], af[im][1], af[im][2], af[im][3],
                            aB + (wm * 32 + im * 16 + rowA) * PITCHB + kb + byteA);
                #pragma unroll
                for (int pr = 0; pr < 2; pr++)
                    ldsm_x4(bf[pr][0], bf[pr][1], bf[pr][2], bf[pr][3],
                            bB + (wn * 32 + pr * 16 + rowB) * PITCHB + kb + byteB);
                #pragma unroll
                for (int im = 0; im < 2; im++)
                    #pragma unroll
                    for (int in = 0; in < 4; in++)
                        mma16816(acc[im][in], af[im], &bf[in >> 1][(in & 1) * 2]);
            }
        }
        __syncthreads();   // all A-tile ldsm reads done before sign overwrite

        // ---- signs * c -> smem (reuse A-hi region), then coalesced to Kaug
        #pragma unroll
        for (int im = 0; im < 2; im++) {
            int r0 = wm * 32 + im * 16 + tq;
            float ca = cs[r0], cb2 = cs[r0 + 8];
            #pragma unroll
            for (int in = 0; in < 4; in++) {
                int t = wn * 32 + in * 8 + tn2;
                *(uint32_t*)(sm + SM_AH + r0 * PITCHB + t * 2) =
                    h2pack(acc[im][in][0] >= 0.0f ? ca : -ca,
                           acc[im][in][1] >= 0.0f ? ca : -ca);
                *(uint32_t*)(sm + SM_AH + (r0 + 8) * PITCHB + t * 2) =
                    h2pack(acc[im][in][2] >= 0.0f ? cb2 : -cb2,
                           acc[im][in][3] >= 0.0f ? cb2 : -cb2);
            }
        }
        __syncthreads();

        // 128 rows x 16 uint4 (256 B of signs per key) = 2048 uint4
        #pragma unroll
        for (int i = 0; i < 4; i++) {
            int idx = tid + i * PREP_THREADS;
            int r = idx >> 4, u = idx & 15;
            uint4 v = *(const uint4*)(sm + SM_AH + r * PITCHB + u * 16);
            g_Kaug4[(size_t)(key0 + r) * (KH / 8) + 16 + u] = v;
        }
        __syncthreads();   // before next tile's phase-1 smem writes
    }
}

// ================================================================ kernel 4
// out[512, 131072] = Qaug @ Kaug^T, K=256 — PROVEN fp32-acc config (112 us,
// measured 3x): CTA 128x128, 256 thr, 8 warps = 2(M)x4(N), warp tile 64x32,
// double-buffered cp.async, 2 CTAs/SM.
#define GE_STAGE 32768             // A 16KB + B 16KB
#define GE_SMEM  (2 * GE_STAGE)
__global__ void __launch_bounds__(256) k_gemm(float* __restrict__ out) {
    extern __shared__ char sm[];
    uint32_t sb = smem_u32(sm);
    int tid = threadIdx.x, wid = tid >> 5, lane = tid & 31;
    int nstrip = blockIdx.x >> 2;       // N-major: 4 M-tiles adjacent share B via L2
    int mtile  = blockIdx.x & 3;
    int key0 = nstrip * TN;

    int wm = wid >> 2, wn = wid & 3;    // warp tile: rows wm*64.., cols wn*32..

    int rowA = (lane & 7) + ((lane >> 3) & 1) * 8;   // A frags
    int byteA = (lane >> 4) * 16;
    int rowB = (lane & 7) + (lane >> 4) * 8;         // B frags
    int byteB = ((lane >> 3) & 1) * 16;

    float acc[4][4][4];
    #pragma unroll
    for (int i = 0; i < 4; i++)
        #pragma unroll
        for (int j = 0; j < 4; j++)
            #pragma unroll
            for (int r = 0; r < 4; r++) acc[i][j][r] = 0.0f;

    const uint4* QA = g_Qaug4;
    const uint4* KA = g_Kaug4;

    // chunk c covers fp16 cols [c*64, c*64+64) = uint4 [c*8, c*8+8) of the 32/row
    #define PREFETCH(c, buf) do { \
        int col8_ = (c) * 8; \
        uint32_t base_ = sb + (buf) * GE_STAGE; \
        _Pragma("unroll") \
        for (int it_ = 0; it_ < 8; it_++) { \
            int idx_ = tid + it_ * 256; \
            int half_ = idx_ >> 10; \
            int w_ = idx_ & 1023; \
            int row_ = w_ >> 3, u_ = w_ & 7; \
            const uint4* gp_; \
            if (half_ == 0) gp_ = QA + (size_t)(mtile * TM + row_) * 32 + col8_ + u_; \
            else            gp_ = KA + (size_t)(key0 + row_) * 32 + col8_ + u_; \
            uint32_t off_ = ((uint32_t)(row_ >> 3) << 10) | ((uint32_t)(row_ & 7) << 7) | ((uint32_t)u_ << 4); \
            off_ = SWZ128(off_); \
            cp_async16(base_ + half_ * 16384 + off_, gp_); \
        } \
        CP_COMMIT(); \
    } while (0)

    PREFETCH(0, 0);

    for (int c = 0; c < NCHUNK; c++) {
        if (c + 1 < NCHUNK) { PREFETCH(c + 1, (c + 1) & 1); CP_WAIT(1); }
        else                { CP_WAIT(0); }
        __syncthreads();

        uint32_t aBase = sb + (c & 1) * GE_STAGE;
        uint32_t bBase = aBase + 16384;

        #pragma unroll
        for (int k16 = 0; k16 < 4; k16++) {
            int kb = k16 * 32;
            uint32_t af[4][4], bf[2][4];
            #pragma unroll
            for (int im = 0; im < 4; im++) {
                int r = wm * 64 + im * 16 + rowA;
                uint32_t off = ((uint32_t)(r >> 3) << 10) | ((uint32_t)(r & 7) << 7) |
                               (uint32_t)(kb + byteA);
                ldsm_x4(af[im][0], af[im][1], af[im][2], af[im][3], aBase + SWZ128(off));
            }
            #pragma unroll
            for (int pr = 0; pr < 2; pr++) {
                int r = wn * 32 + pr * 16 + rowB;
                uint32_t off = ((uint32_t)(r >> 3) << 10) | ((uint32_t)(r & 7) << 7) |
                               (uint32_t)(kb + byteB);
                ldsm_x4(bf[pr][0], bf[pr][1], bf[pr][2], bf[pr][3], bBase + SWZ128(off));
            }
            #pragma unroll
            for (int im = 0; im < 4; im++) {
                #pragma unroll
                for (int in = 0; in < 4; in++) {
                    mma16816(acc[im][in], af[im], &bf[in >> 1][(in & 1) * 2]);
                }
            }
        }
        __syncthreads();
    }

    // ---- epilogue: direct fp32 stores ----
    int tq = lane >> 2, tn2 = (lane & 3) * 2;
    #pragma unroll
    for (int im = 0; im < 4; im++) {
        #pragma unroll
        for (int in = 0; in < 4; in++) {
            int m = mtile * TM + wm * 64 + im * 16 + tq;
            int n = key0 + wn * 32 + in * 8 + tn2;
            float2 v0 = make_float2(acc[im][in][0], acc[im][in][1]);
            float2 v1 = make_float2(acc[im][in][2], acc[im][in][3]);
            *(float2*)(out + (size_t)m * NKEY + n) = v0;
            *(float2*)(out + (size_t)(m + 8) * NKEY + n) = v1;
        }
    }
    #undef PREFETCH
}

// ================================================================ launch
extern "C" void kernel_launch(void* const* d_in, const int* in_sizes, int n_in,
                              void* d_out, int out_size) {
    const float* query = (const float*)d_in[0];
    const float* keys  = (const float*)d_in[1];
    const float* cb    = (const float*)d_in[2];
    const float* S     = (const float*)d_in[3];
    float* out = (float*)d_out;

    static bool attr_done = false;
    if (!attr_done) {
        cudaFuncSetAttribute(k_prep_keys, cudaFuncAttributeMaxDynamicSharedMemorySize, PF_SMEM);
        cudaFuncSetAttribute(k_gemm, cudaFuncAttributeMaxDynamicSharedMemorySize, GE_SMEM);
        attr_done = true;
    }

    k_prep_S<<<DQ, DQ>>>(S);
    k_prep_query<<<QN, 128>>>(query, S);
    k_prep_keys<<<PREP_GRID, PREP_THREADS, PF_SMEM>>>(keys, cb);
    k_gemm<<<(NKEY / TN) * (QN / TM), 256, GE_SMEM>>>(out);
}